// round 6
// baseline (speedup 1.0000x reference)
#include <cuda_runtime.h>
#include <cuda_fp16.h>
#include <cstdint>

// Problem constants (fixed shapes per reference)
#define TOKENS 8192
#define INF    4096
#define OUTF   4096

// ---------------- device scratch (static globals; no runtime allocation) ----
__device__ float          g_Wf32[(size_t)OUTF * INF];   // 64 MiB dense accumulate
__device__ unsigned short g_Wh  [(size_t)OUTF * INF];   // 32 MiB fp16 W
__device__ unsigned short g_Xh  [(size_t)TOKENS * INF]; // 64 MiB fp16 x
__device__ int            g_idx32_flag;                 // 1 => indices are int32

// ---------------- helpers ---------------------------------------------------
__device__ __forceinline__ uint32_t smem_to_u32(const void* p) {
    uint32_t a;
    asm("{ .reg .u64 t; cvta.to.shared.u64 t, %1; cvt.u32.u64 %0, t; }"
        : "=r"(a) : "l"(p));
    return a;
}

#define SMEM_SWIZZLE_128B(byte_offset) \
    ((byte_offset) ^ (((byte_offset) >> 3) & 0x70))

__device__ __forceinline__ void cp_async_16(uint32_t saddr, const void* gaddr) {
    asm volatile("cp.async.cg.shared.global [%0], [%1], 16;"
                 :: "r"(saddr), "l"(gaddr) : "memory");
}
#define CP_ASYNC_COMMIT() asm volatile("cp.async.commit_group;" ::: "memory")
#define CP_ASYNC_WAIT(N)  asm volatile("cp.async.wait_group %0;" :: "n"(N) : "memory")

__device__ __forceinline__ void ldsm_x4(uint32_t r[4], uint32_t addr) {
    asm volatile("ldmatrix.sync.aligned.m8n8.x4.shared.b16 {%0,%1,%2,%3}, [%4];"
                 : "=r"(r[0]), "=r"(r[1]), "=r"(r[2]), "=r"(r[3]) : "r"(addr));
}

__device__ __forceinline__ void mma16816(float c[4], const uint32_t a[4],
                                         uint32_t b0, uint32_t b1) {
    asm volatile(
        "mma.sync.aligned.m16n8k16.row.col.f32.f16.f16.f32 "
        "{%0,%1,%2,%3}, {%4,%5,%6,%7}, {%8,%9}, {%0,%1,%2,%3};"
        : "+f"(c[0]), "+f"(c[1]), "+f"(c[2]), "+f"(c[3])
        : "r"(a[0]), "r"(a[1]), "r"(a[2]), "r"(a[3]), "r"(b0), "r"(b1));
}

// ---------------- prep kernels ---------------------------------------------
__global__ void zero_w_kernel() {
    size_t i = (size_t)blockIdx.x * blockDim.x + threadIdx.x;
    float4 z = make_float4(0.f, 0.f, 0.f, 0.f);
    reinterpret_cast<float4*>(g_Wf32)[i] = z;
    if (blockIdx.x == 0 && threadIdx.x == 0) g_idx32_flag = 0;
}

// Detect index dtype. Read the first nnz elements AS int64: that view spans
// exactly 8*nnz bytes, which is in-bounds whether the buffer holds 2*nnz
// int32 (8*nnz B) or 2*nnz int64 (16*nnz B). If the data is really int64 row
// indices, every value is in [0, OUTF). If it is int32, each int64 lane packs
// two row indices (a + b*2^32) and goes out of range as soon as b != 0.
__global__ void detect_idx_kernel(const long long* __restrict__ idx, int nnz) {
    int i = blockIdx.x * blockDim.x + threadIdx.x;
    if (i < nnz) {
        long long v = idx[i];
        if (v < 0 || v >= OUTF) atomicOr(&g_idx32_flag, 1);
    }
}

__global__ void scatter_kernel(const void* __restrict__ idx_raw,
                               const float* __restrict__ w, int nnz) {
    int i = blockIdx.x * blockDim.x + threadIdx.x;
    if (i >= nnz) return;
    long long r, c;
    if (g_idx32_flag) {
        const int* p = (const int*)idx_raw;
        r = p[i];
        c = p[(size_t)nnz + i];
    } else {
        const long long* p = (const long long*)idx_raw;
        r = p[i];
        c = p[(size_t)nnz + i];
    }
    if (r >= 0 && r < OUTF && c >= 0 && c < INF)
        atomicAdd(&g_Wf32[(size_t)r * INF + c], w[i]);
}

__global__ void convert_w_kernel() {
    size_t i = (size_t)blockIdx.x * blockDim.x + threadIdx.x;
    float4 v = reinterpret_cast<const float4*>(g_Wf32)[i];
    __half2 lo = __floats2half2_rn(v.x, v.y);
    __half2 hi = __floats2half2_rn(v.z, v.w);
    uint2 o;
    o.x = *reinterpret_cast<uint32_t*>(&lo);
    o.y = *reinterpret_cast<uint32_t*>(&hi);
    reinterpret_cast<uint2*>(g_Wh)[i] = o;
}

__global__ void convert_x_kernel(const float* __restrict__ x) {
    size_t i = (size_t)blockIdx.x * blockDim.x + threadIdx.x;
    float4 v = reinterpret_cast<const float4*>(x)[i];
    __half2 lo = __floats2half2_rn(v.x, v.y);
    __half2 hi = __floats2half2_rn(v.z, v.w);
    uint2 o;
    o.x = *reinterpret_cast<uint32_t*>(&lo);
    o.y = *reinterpret_cast<uint32_t*>(&hi);
    reinterpret_cast<uint2*>(g_Xh)[i] = o;
}

// ---------------- GEMM kernel (mma.sync m16n8k16, Ampere-style) -------------
// CTA tile 256(M) x 128(N) x 64(K); 8 warps as 4(M) x 2(N), warp tile 64x64.
// 4-stage cp.async pipeline; smem rows are 64 halves = 128 B, SW128-swizzled.

static constexpr int CTA_M  = 256;
static constexpr int CTA_N  = 128;
static constexpr int CTA_K  = 64;
static constexpr int STAGES = 4;
static constexpr int KITERS = INF / CTA_K;   // 64

static constexpr int A_BYTES      = CTA_M * CTA_K * 2;   // 32768
static constexpr int B_BYTES      = CTA_N * CTA_K * 2;   // 16384
static constexpr int STAGE_BYTES  = A_BYTES + B_BYTES;   // 49152
static constexpr int GEMM_SMEM    = STAGES * STAGE_BYTES; // 196608

__device__ __forceinline__ void load_stage(uint32_t sbase, int tid,
                                           const unsigned short* __restrict__ Xp,
                                           const unsigned short* __restrict__ Wp,
                                           int slot, int kb) {
    const uint32_t stage = sbase + slot * STAGE_BYTES;
    const int kcol = kb * CTA_K;
#pragma unroll
    for (int j = 0; j < 12; j++) {              // 3072 16B chunks / 256 threads
        int c = tid + j * 256;
        if (c < 2048) {                         // A: 256 rows x 8 chunks
            int row = c >> 3, ch = c & 7;
            const unsigned short* g = Xp + (size_t)row * INF + kcol + ch * 8;
            cp_async_16(stage + SMEM_SWIZZLE_128B(row * 128 + ch * 16), g);
        } else {                                // B: 128 rows x 8 chunks
            int cc = c - 2048;
            int row = cc >> 3, ch = cc & 7;
            const unsigned short* g = Wp + (size_t)row * INF + kcol + ch * 8;
            cp_async_16(stage + A_BYTES + SMEM_SWIZZLE_128B(row * 128 + ch * 16), g);
        }
    }
    CP_ASYNC_COMMIT();
}

__global__ void __launch_bounds__(256)
gemm_kernel(const float* __restrict__ bias, float* __restrict__ out) {
    extern __shared__ char smem[];
    const uint32_t sbase = smem_to_u32(smem);
    const int tid  = threadIdx.x;
    const int wid  = tid >> 5;
    const int lane = tid & 31;
    const int wm = wid & 3;       // 4 warps along M
    const int wn = wid >> 2;      // 2 warps along N

    // L2-friendly raster: GROUP=4 m-tiles per n-sweep
    const int grid_n = OUTF / CTA_N;   // 32
    const int GROUP  = 4;
    const int per    = GROUP * grid_n;
    const int g      = blockIdx.x / per;
    const int rem    = blockIdx.x % per;
    const int mtile  = g * GROUP + (rem % GROUP);
    const int ntile  = rem / GROUP;
    const int m0 = mtile * CTA_M;
    const int n0 = ntile * CTA_N;

    const unsigned short* Xp = g_Xh + (size_t)m0 * INF;
    const unsigned short* Wp = g_Wh + (size_t)n0 * INF;

    // per-lane ldmatrix base offsets (pre-swizzle, within A / B regions)
    // A x4: lanes 0-15 -> m rows 0-15 (k bytes 0), lanes 16-31 -> same rows, k bytes +16
    const int a_base = (wm * 64 + (lane & 15)) * 128 + ((lane >> 4) << 4);
    // B x4: mat0 (n0-7,k0-7), mat1 (n0-7,k8-15), mat2 (n8-15,k0-7), mat3 (n8-15,k8-15)
    const int b_base = (wn * 64 + ((lane >> 4) << 3) + (lane & 7)) * 128
                     + (((lane >> 3) & 1) << 4);

    float acc[4][8][4];
#pragma unroll
    for (int mt = 0; mt < 4; mt++)
#pragma unroll
        for (int nt = 0; nt < 8; nt++)
#pragma unroll
            for (int k = 0; k < 4; k++) acc[mt][nt][k] = 0.f;

    // prologue: fill 3 of 4 stages
    load_stage(sbase, tid, Xp, Wp, 0, 0);
    load_stage(sbase, tid, Xp, Wp, 1, 1);
    load_stage(sbase, tid, Xp, Wp, 2, 2);

    for (int it = 0; it < KITERS; it++) {
        CP_ASYNC_WAIT(2);            // stage `it` data resident
        __syncthreads();             // all warps done with stage it-1 too

        // prefetch next tile into the free slot
        if (it + 3 < KITERS) {
            load_stage(sbase, tid, Xp, Wp, (it + 3) & 3, it + 3);
        } else {
            CP_ASYNC_COMMIT();       // keep group bookkeeping uniform
        }

        const uint32_t SA = sbase + (it & 3) * STAGE_BYTES;
        const uint32_t SB = SA + A_BYTES;

#pragma unroll
        for (int ks = 0; ks < 4; ks++) {
            uint32_t a[4][4];
#pragma unroll
            for (int mt = 0; mt < 4; mt++) {
                int off = a_base + mt * 2048 + ks * 32;
                ldsm_x4(a[mt], SA + SMEM_SWIZZLE_128B(off));
            }
            uint32_t b[4][4];
#pragma unroll
            for (int bt = 0; bt < 4; bt++) {
                int off = b_base + bt * 2048 + ks * 32;
                ldsm_x4(b[bt], SB + SMEM_SWIZZLE_128B(off));
            }
#pragma unroll
            for (int mt = 0; mt < 4; mt++)
#pragma unroll
                for (int nt = 0; nt < 8; nt++) {
                    int bt = nt >> 1, pr = nt & 1;
                    mma16816(acc[mt][nt], a[mt], b[bt][pr * 2], b[bt][pr * 2 + 1]);
                }
        }
    }

    // ---------------- epilogue: add bias, store f32 -------------------------
    {
        float2 bv[8];
#pragma unroll
        for (int nt = 0; nt < 8; nt++) {
            int n = n0 + wn * 64 + nt * 8 + (lane & 3) * 2;
            bv[nt].x = __ldg(bias + n);
            bv[nt].y = __ldg(bias + n + 1);
        }
#pragma unroll
        for (int mt = 0; mt < 4; mt++) {
#pragma unroll
            for (int r = 0; r < 2; r++) {
                int row = m0 + wm * 64 + mt * 16 + (lane >> 2) + r * 8;
                float* orow = out + (size_t)row * OUTF + n0 + wn * 64 + (lane & 3) * 2;
#pragma unroll
                for (int nt = 0; nt < 8; nt++) {
                    float2 v;
                    v.x = acc[mt][nt][r * 2 + 0] + bv[nt].x;
                    v.y = acc[mt][nt][r * 2 + 1] + bv[nt].y;
                    *reinterpret_cast<float2*>(orow + nt * 8) = v;
                }
            }
        }
    }
}

// ---------------- launcher --------------------------------------------------
extern "C" void kernel_launch(void* const* d_in, const int* in_sizes, int n_in,
                              void* d_out, int out_size) {
    const float* x    = (const float*)d_in[0];      // [8192, 4096] f32
    const float* w    = (const float*)d_in[1];      // [NNZ] f32
    const float* bias = (const float*)d_in[2];      // [4096] f32
    const void*  idx  = d_in[3];                    // [2, NNZ] int32 OR int64
    float* out = (float*)d_out;                     // [8192, 4096] f32
    const int nnz = in_sizes[1];

    // 1) zero dense W accumulator (+ reset dtype flag)
    zero_w_kernel<<<(OUTF * INF / 4) / 256, 256>>>();
    // 2) detect whether indices are int32 (jax x64 disabled) or true int64
    detect_idx_kernel<<<(nnz + 255) / 256, 256>>>((const long long*)idx, nnz);
    // 3) scatter-add COO (duplicates summed), dtype-robust, bounds-guarded
    scatter_kernel<<<(nnz + 255) / 256, 256>>>(idx, w, nnz);
    // 4) convert W to fp16
    convert_w_kernel<<<(OUTF * INF / 4) / 256, 256>>>();
    // 5) convert x to fp16
    convert_x_kernel<<<((size_t)TOKENS * INF / 4) / 256, 256>>>(x);

    // 6) HMMA GEMM: out = x @ W^T + bias
    cudaFuncSetAttribute(gemm_kernel,
                         cudaFuncAttributeMaxDynamicSharedMemorySize, GEMM_SMEM);
    const int grid = (TOKENS / CTA_M) * (OUTF / CTA_N);  // 32 * 32 = 1024
    gemm_kernel<<<grid, 256, GEMM_SMEM>>>(bias, out);
}

// round 7
// speedup vs baseline: 1.0963x; 1.0963x over previous
#include <cuda_runtime.h>
#include <cuda_fp16.h>
#include <cstdint>

// Problem constants (fixed shapes per reference)
#define TOKENS 8192
#define INF    4096
#define OUTF   4096

// ---------------- device scratch (static globals; no runtime allocation) ----
__device__ float          g_Wf32[(size_t)OUTF * INF];   // 64 MiB dense accumulate
__device__ unsigned short g_Wh  [(size_t)OUTF * INF];   // 32 MiB fp16 W
__device__ unsigned short g_Xh  [(size_t)TOKENS * INF]; // 64 MiB fp16 x
__device__ int            g_idx32_flag;                 // 1 => indices are int32

// ---------------- helpers ---------------------------------------------------
__device__ __forceinline__ uint32_t smem_to_u32(const void* p) {
    uint32_t a;
    asm("{ .reg .u64 t; cvta.to.shared.u64 t, %1; cvt.u32.u64 %0, t; }"
        : "=r"(a) : "l"(p));
    return a;
}

#define SMEM_SWIZZLE_128B(byte_offset) \
    ((byte_offset) ^ (((byte_offset) >> 3) & 0x70))

__device__ __forceinline__ void cp_async_16(uint32_t saddr, const void* gaddr) {
    asm volatile("cp.async.cg.shared.global [%0], [%1], 16;"
                 :: "r"(saddr), "l"(gaddr) : "memory");
}
#define CP_ASYNC_COMMIT() asm volatile("cp.async.commit_group;" ::: "memory")
#define CP_ASYNC_WAIT(N)  asm volatile("cp.async.wait_group %0;" :: "n"(N) : "memory")

__device__ __forceinline__ void ldsm_x4(uint32_t r[4], uint32_t addr) {
    asm volatile("ldmatrix.sync.aligned.m8n8.x4.shared.b16 {%0,%1,%2,%3}, [%4];"
                 : "=r"(r[0]), "=r"(r[1]), "=r"(r[2]), "=r"(r[3]) : "r"(addr));
}

__device__ __forceinline__ void mma16816(float c[4], const uint32_t a[4],
                                         uint32_t b0, uint32_t b1) {
    asm volatile(
        "mma.sync.aligned.m16n8k16.row.col.f32.f16.f16.f32 "
        "{%0,%1,%2,%3}, {%4,%5,%6,%7}, {%8,%9}, {%0,%1,%2,%3};"
        : "+f"(c[0]), "+f"(c[1]), "+f"(c[2]), "+f"(c[3])
        : "r"(a[0]), "r"(a[1]), "r"(a[2]), "r"(a[3]), "r"(b0), "r"(b1));
}

// ---------------- prep kernels ---------------------------------------------
__global__ void zero_w_kernel() {   // grid-stride x2, float4
    size_t i = (size_t)blockIdx.x * blockDim.x + threadIdx.x;
    size_t stride = (size_t)gridDim.x * blockDim.x;
    float4 z = make_float4(0.f, 0.f, 0.f, 0.f);
    reinterpret_cast<float4*>(g_Wf32)[i] = z;
    reinterpret_cast<float4*>(g_Wf32)[i + stride] = z;
    if (blockIdx.x == 0 && threadIdx.x == 0) g_idx32_flag = 0;
}

// Detect index dtype (see round-3 analysis): reading the first nnz entries as
// int64 is in-bounds under both interpretations; true-int64 row indices are
// all < OUTF, packed-int32 pairs blow past it as soon as the high lane != 0.
__global__ void detect_idx_kernel(const long long* __restrict__ idx, int nnz) {
    int i = blockIdx.x * blockDim.x + threadIdx.x;
    if (i < nnz) {
        long long v = idx[i];
        if (v < 0 || v >= OUTF) atomicOr(&g_idx32_flag, 1);
    }
}

__global__ void scatter_kernel(const void* __restrict__ idx_raw,
                               const float* __restrict__ w, int nnz) {
    int i = blockIdx.x * blockDim.x + threadIdx.x;
    if (i >= nnz) return;
    long long r, c;
    if (g_idx32_flag) {
        const int* p = (const int*)idx_raw;
        r = p[i];
        c = p[(size_t)nnz + i];
    } else {
        const long long* p = (const long long*)idx_raw;
        r = p[i];
        c = p[(size_t)nnz + i];
    }
    if (r >= 0 && r < OUTF && c >= 0 && c < INF)
        atomicAdd(&g_Wf32[(size_t)r * INF + c], w[i]);
}

__device__ __forceinline__ uint2 f4_to_h4(float4 v) {
    __half2 lo = __floats2half2_rn(v.x, v.y);
    __half2 hi = __floats2half2_rn(v.z, v.w);
    uint2 o;
    o.x = *reinterpret_cast<uint32_t*>(&lo);
    o.y = *reinterpret_cast<uint32_t*>(&hi);
    return o;
}

__global__ void convert_w_kernel() {  // grid-stride x2 for MLP
    size_t i = (size_t)blockIdx.x * blockDim.x + threadIdx.x;
    size_t stride = (size_t)gridDim.x * blockDim.x;
    float4 v0 = reinterpret_cast<const float4*>(g_Wf32)[i];
    float4 v1 = reinterpret_cast<const float4*>(g_Wf32)[i + stride];
    reinterpret_cast<uint2*>(g_Wh)[i]          = f4_to_h4(v0);
    reinterpret_cast<uint2*>(g_Wh)[i + stride] = f4_to_h4(v1);
}

__global__ void convert_x_kernel(const float* __restrict__ x) {
    size_t i = (size_t)blockIdx.x * blockDim.x + threadIdx.x;
    size_t stride = (size_t)gridDim.x * blockDim.x;
    float4 v0 = reinterpret_cast<const float4*>(x)[i];
    float4 v1 = reinterpret_cast<const float4*>(x)[i + stride];
    reinterpret_cast<uint2*>(g_Xh)[i]          = f4_to_h4(v0);
    reinterpret_cast<uint2*>(g_Xh)[i + stride] = f4_to_h4(v1);
}

// ---------------- GEMM kernel (mma.sync m16n8k16, Ampere-style) -------------
// CTA tile 256(M) x 128(N) x 64(K); 8 warps as 4(M) x 2(N), warp tile 64x64.
// 4-stage cp.async pipeline; smem rows are 64 halves = 128 B, SW128-swizzled.
// Inner loop register-double-buffers ldmatrix fragments against the HMMAs.

static constexpr int CTA_M  = 256;
static constexpr int CTA_N  = 128;
static constexpr int CTA_K  = 64;
static constexpr int KITERS = INF / CTA_K;   // 64

static constexpr int A_BYTES      = CTA_M * CTA_K * 2;    // 32768
static constexpr int B_BYTES      = CTA_N * CTA_K * 2;    // 16384
static constexpr int STAGE_BYTES  = A_BYTES + B_BYTES;    // 49152
static constexpr int GEMM_SMEM    = 4 * STAGE_BYTES;      // 196608

__device__ __forceinline__ void load_stage(uint32_t sbase, int tid,
                                           const unsigned short* __restrict__ Xp,
                                           const unsigned short* __restrict__ Wp,
                                           int slot, int kb) {
    const uint32_t stage = sbase + slot * STAGE_BYTES;
    const int kcol = kb * CTA_K;
#pragma unroll
    for (int j = 0; j < 12; j++) {              // 3072 16B chunks / 256 threads
        int c = tid + j * 256;
        if (c < 2048) {                         // A: 256 rows x 8 chunks
            int row = c >> 3, ch = c & 7;
            const unsigned short* g = Xp + (size_t)row * INF + kcol + ch * 8;
            cp_async_16(stage + SMEM_SWIZZLE_128B(row * 128 + ch * 16), g);
        } else {                                // B: 128 rows x 8 chunks
            int cc = c - 2048;
            int row = cc >> 3, ch = cc & 7;
            const unsigned short* g = Wp + (size_t)row * INF + kcol + ch * 8;
            cp_async_16(stage + A_BYTES + SMEM_SWIZZLE_128B(row * 128 + ch * 16), g);
        }
    }
    CP_ASYNC_COMMIT();
}

__global__ void __launch_bounds__(256, 1)
gemm_kernel(const float* __restrict__ bias, float* __restrict__ out) {
    extern __shared__ char smem[];
    const uint32_t sbase = smem_to_u32(smem);
    const int tid  = threadIdx.x;
    const int wid  = tid >> 5;
    const int lane = tid & 31;
    const int wm = wid & 3;       // 4 warps along M
    const int wn = wid >> 2;      // 2 warps along N

    // L2-friendly raster: GROUP=8 m-tiles per n-sweep (W DRAM reads 4x total)
    const int grid_n = OUTF / CTA_N;   // 32
    const int GROUP  = 8;
    const int per    = GROUP * grid_n; // 256
    const int g      = blockIdx.x / per;
    const int rem    = blockIdx.x % per;
    const int mtile  = g * GROUP + (rem % GROUP);
    const int ntile  = rem / GROUP;
    const int m0 = mtile * CTA_M;
    const int n0 = ntile * CTA_N;

    const unsigned short* Xp = g_Xh + (size_t)m0 * INF;
    const unsigned short* Wp = g_Wh + (size_t)n0 * INF;

    // per-lane ldmatrix base offsets (pre-swizzle, within A / B regions)
    const int a_base = (wm * 64 + (lane & 15)) * 128 + ((lane >> 4) << 4);
    const int b_base = (wn * 64 + ((lane >> 4) << 3) + (lane & 7)) * 128
                     + (((lane >> 3) & 1) << 4);

    float acc[4][8][4];
#pragma unroll
    for (int mt = 0; mt < 4; mt++)
#pragma unroll
        for (int nt = 0; nt < 8; nt++)
#pragma unroll
            for (int k = 0; k < 4; k++) acc[mt][nt][k] = 0.f;

    // prologue: fill 3 of 4 stages
    load_stage(sbase, tid, Xp, Wp, 0, 0);
    load_stage(sbase, tid, Xp, Wp, 1, 1);
    load_stage(sbase, tid, Xp, Wp, 2, 2);

    uint32_t a[2][4][4], b[2][4][4];

    for (int it = 0; it < KITERS; it++) {
        CP_ASYNC_WAIT(2);            // stage `it` data resident
        __syncthreads();             // all warps done with stage it-1 too

        // prefetch next K-tile into the free slot
        if (it + 3 < KITERS) {
            load_stage(sbase, tid, Xp, Wp, (it + 3) & 3, it + 3);
        } else {
            CP_ASYNC_COMMIT();       // keep group bookkeeping uniform
        }

        const uint32_t SA = sbase + (it & 3) * STAGE_BYTES;
        const uint32_t SB = SA + A_BYTES;

        // preload ks=0 fragments
#pragma unroll
        for (int mt = 0; mt < 4; mt++)
            ldsm_x4(a[0][mt], SA + SMEM_SWIZZLE_128B(a_base + mt * 2048));
#pragma unroll
        for (int bt = 0; bt < 4; bt++)
            ldsm_x4(b[0][bt], SB + SMEM_SWIZZLE_128B(b_base + bt * 2048));

#pragma unroll
        for (int ks = 0; ks < 4; ks++) {
            const int cur = ks & 1, nxt = cur ^ 1;
            if (ks < 3) {            // prefetch ks+1 fragments behind the mmas
#pragma unroll
                for (int mt = 0; mt < 4; mt++)
                    ldsm_x4(a[nxt][mt],
                            SA + SMEM_SWIZZLE_128B(a_base + mt * 2048 + (ks + 1) * 32));
#pragma unroll
                for (int bt = 0; bt < 4; bt++)
                    ldsm_x4(b[nxt][bt],
                            SB + SMEM_SWIZZLE_128B(b_base + bt * 2048 + (ks + 1) * 32));
            }
#pragma unroll
            for (int mt = 0; mt < 4; mt++)
#pragma unroll
                for (int nt = 0; nt < 8; nt++) {
                    int bt = nt >> 1, pr = nt & 1;
                    mma16816(acc[mt][nt], a[cur][mt],
                             b[cur][bt][pr * 2], b[cur][bt][pr * 2 + 1]);
                }
        }
    }

    // ---------------- epilogue: add bias, store f32 -------------------------
    {
        float2 bv[8];
#pragma unroll
        for (int nt = 0; nt < 8; nt++) {
            int n = n0 + wn * 64 + nt * 8 + (lane & 3) * 2;
            bv[nt].x = __ldg(bias + n);
            bv[nt].y = __ldg(bias + n + 1);
        }
#pragma unroll
        for (int mt = 0; mt < 4; mt++) {
#pragma unroll
            for (int r = 0; r < 2; r++) {
                int row = m0 + wm * 64 + mt * 16 + (lane >> 2) + r * 8;
                float* orow = out + (size_t)row * OUTF + n0 + wn * 64 + (lane & 3) * 2;
#pragma unroll
                for (int nt = 0; nt < 8; nt++) {
                    float2 v;
                    v.x = acc[mt][nt][r * 2 + 0] + bv[nt].x;
                    v.y = acc[mt][nt][r * 2 + 1] + bv[nt].y;
                    *reinterpret_cast<float2*>(orow + nt * 8) = v;
                }
            }
        }
    }
}

// ---------------- launcher --------------------------------------------------
extern "C" void kernel_launch(void* const* d_in, const int* in_sizes, int n_in,
                              void* d_out, int out_size) {
    const float* x    = (const float*)d_in[0];      // [8192, 4096] f32
    const float* w    = (const float*)d_in[1];      // [NNZ] f32
    const float* bias = (const float*)d_in[2];      // [4096] f32
    const void*  idx  = d_in[3];                    // [2, NNZ] int32 OR int64
    float* out = (float*)d_out;                     // [8192, 4096] f32
    const int nnz = in_sizes[1];

    // 1) zero dense W accumulator (+ reset dtype flag)
    zero_w_kernel<<<(OUTF * INF / 8) / 256, 256>>>();
    // 2) detect int32-vs-int64 indices
    detect_idx_kernel<<<(nnz + 255) / 256, 256>>>((const long long*)idx, nnz);
    // 3) scatter-add COO (duplicates summed), dtype-robust, bounds-guarded
    scatter_kernel<<<(nnz + 255) / 256, 256>>>(idx, w, nnz);
    // 4) convert W to fp16
    convert_w_kernel<<<(OUTF * INF / 8) / 256, 256>>>();
    // 5) convert x to fp16
    convert_x_kernel<<<((size_t)TOKENS * INF / 8) / 256, 256>>>(x);

    // 6) HMMA GEMM: out = x @ W^T + bias
    cudaFuncSetAttribute(gemm_kernel,
                         cudaFuncAttributeMaxDynamicSharedMemorySize, GEMM_SMEM);
    const int grid = (TOKENS / CTA_M) * (OUTF / CTA_N);  // 32 * 32 = 1024
    gemm_kernel<<<grid, 256, GEMM_SMEM>>>(bias, out);
}

// round 10
// speedup vs baseline: 1.1405x; 1.0403x over previous
#include <cuda_runtime.h>
#include <cuda_fp16.h>
#include <cstdint>

// Problem constants (fixed shapes per reference)
#define TOKENS 8192
#define INF    4096
#define OUTF   4096

// ---------------- device scratch (static globals; no runtime allocation) ----
__device__ __half         g_Wh[(size_t)OUTF * INF];     // 32 MiB fp16 W (scatter target)
__device__ unsigned short g_Xh[(size_t)TOKENS * INF];   // 64 MiB fp16 x
__device__ int            g_idx32_flag;                 // 1 => indices are int32

// ---------------- helpers ---------------------------------------------------
__device__ __forceinline__ uint32_t smem_to_u32(const void* p) {
    uint32_t a;
    asm("{ .reg .u64 t; cvta.to.shared.u64 t, %1; cvt.u32.u64 %0, t; }"
        : "=r"(a) : "l"(p));
    return a;
}

#define SMEM_SWIZZLE_128B(byte_offset) \
    ((byte_offset) ^ (((byte_offset) >> 3) & 0x70))

__device__ __forceinline__ void cp_async_16(uint32_t saddr, const void* gaddr) {
    asm volatile("cp.async.cg.shared.global [%0], [%1], 16;"
                 :: "r"(saddr), "l"(gaddr) : "memory");
}
#define CP_ASYNC_COMMIT() asm volatile("cp.async.commit_group;" ::: "memory")
#define CP_ASYNC_WAIT(N)  asm volatile("cp.async.wait_group %0;" :: "n"(N) : "memory")

__device__ __forceinline__ void ldsm_x4(uint32_t r[4], uint32_t addr) {
    asm volatile("ldmatrix.sync.aligned.m8n8.x4.shared.b16 {%0,%1,%2,%3}, [%4];"
                 : "=r"(r[0]), "=r"(r[1]), "=r"(r[2]), "=r"(r[3]) : "r"(addr));
}

__device__ __forceinline__ void mma16816(float c[4], const uint32_t a[4],
                                         uint32_t b0, uint32_t b1) {
    asm volatile(
        "mma.sync.aligned.m16n8k16.row.col.f32.f16.f16.f32 "
        "{%0,%1,%2,%3}, {%4,%5,%6,%7}, {%8,%9}, {%0,%1,%2,%3};"
        : "+f"(c[0]), "+f"(c[1]), "+f"(c[2]), "+f"(c[3])
        : "r"(a[0]), "r"(a[1]), "r"(a[2]), "r"(a[3]), "r"(b0), "r"(b1));
}

// ---------------- prep kernels ---------------------------------------------
__global__ void zero_wh_kernel() {   // 32 MiB fp16 buffer, uint4 x2 grid-stride
    size_t i = (size_t)blockIdx.x * blockDim.x + threadIdx.x;
    size_t stride = (size_t)gridDim.x * blockDim.x;
    uint4 z = make_uint4(0u, 0u, 0u, 0u);
    reinterpret_cast<uint4*>(g_Wh)[i] = z;
    reinterpret_cast<uint4*>(g_Wh)[i + stride] = z;
    if (blockIdx.x == 0 && threadIdx.x == 0) g_idx32_flag = 0;
}

// Detect index dtype on a 64K-entry prefix (certain for random data): reading
// the prefix as int64 is in-bounds under both interpretations; true-int64 row
// indices are all < OUTF, packed-int32 pairs blow past OUTF as soon as the
// high 32-bit lane is nonzero.
__global__ void detect_idx_kernel(const long long* __restrict__ idx, int n) {
    int i = blockIdx.x * blockDim.x + threadIdx.x;
    if (i < n) {
        long long v = idx[i];
        if (v < 0 || v >= OUTF) atomicOr(&g_idx32_flag, 1);
    }
}

// Scatter-add COO directly into fp16 W (duplicates summed via f16 atomics).
__global__ void scatter_kernel(const void* __restrict__ idx_raw,
                               const float* __restrict__ w, int nnz) {
    int i = blockIdx.x * blockDim.x + threadIdx.x;
    if (i >= nnz) return;
    long long r, c;
    if (g_idx32_flag) {
        const int* p = (const int*)idx_raw;
        r = p[i];
        c = p[(size_t)nnz + i];
    } else {
        const long long* p = (const long long*)idx_raw;
        r = p[i];
        c = p[(size_t)nnz + i];
    }
    if (r >= 0 && r < OUTF && c >= 0 && c < INF)
        atomicAdd(&g_Wh[(size_t)r * INF + c], __float2half(w[i]));
}

__device__ __forceinline__ uint2 f4_to_h4(float4 v) {
    __half2 lo = __floats2half2_rn(v.x, v.y);
    __half2 hi = __floats2half2_rn(v.z, v.w);
    uint2 o;
    o.x = *reinterpret_cast<uint32_t*>(&lo);
    o.y = *reinterpret_cast<uint32_t*>(&hi);
    return o;
}

__global__ void convert_x_kernel(const float* __restrict__ x) {  // ILP x4
    size_t i = (size_t)blockIdx.x * blockDim.x + threadIdx.x;
    size_t stride = (size_t)gridDim.x * blockDim.x;
    float4 v0 = reinterpret_cast<const float4*>(x)[i];
    float4 v1 = reinterpret_cast<const float4*>(x)[i + stride];
    float4 v2 = reinterpret_cast<const float4*>(x)[i + 2 * stride];
    float4 v3 = reinterpret_cast<const float4*>(x)[i + 3 * stride];
    reinterpret_cast<uint2*>(g_Xh)[i]              = f4_to_h4(v0);
    reinterpret_cast<uint2*>(g_Xh)[i + stride]     = f4_to_h4(v1);
    reinterpret_cast<uint2*>(g_Xh)[i + 2 * stride] = f4_to_h4(v2);
    reinterpret_cast<uint2*>(g_Xh)[i + 3 * stride] = f4_to_h4(v3);
}

// ---------------- GEMM kernel (mma.sync m16n8k16, Ampere-style) -------------
// CTA tile 256(M) x 128(N) x 64(K); 8 warps as 4(M) x 2(N), warp tile 64x64.
// 4-stage cp.async pipeline; smem rows are 64 halves = 128 B, SW128-swizzled.
// Inner loop register-double-buffers ldmatrix fragments against the HMMAs.

static constexpr int CTA_M  = 256;
static constexpr int CTA_N  = 128;
static constexpr int CTA_K  = 64;
static constexpr int KITERS = INF / CTA_K;   // 64

static constexpr int A_BYTES      = CTA_M * CTA_K * 2;    // 32768
static constexpr int B_BYTES      = CTA_N * CTA_K * 2;    // 16384
static constexpr int STAGE_BYTES  = A_BYTES + B_BYTES;    // 49152
static constexpr int GEMM_SMEM    = 4 * STAGE_BYTES;      // 196608

__device__ __forceinline__ void load_stage(uint32_t sbase, int tid,
                                           const unsigned short* __restrict__ Xp,
                                           const unsigned short* __restrict__ Wp,
                                           int slot, int kb) {
    const uint32_t stage = sbase + slot * STAGE_BYTES;
    const int kcol = kb * CTA_K;
#pragma unroll
    for (int j = 0; j < 12; j++) {              // 3072 16B chunks / 256 threads
        int c = tid + j * 256;
        if (c < 2048) {                         // A: 256 rows x 8 chunks
            int row = c >> 3, ch = c & 7;
            const unsigned short* g = Xp + (size_t)row * INF + kcol + ch * 8;
            cp_async_16(stage + SMEM_SWIZZLE_128B(row * 128 + ch * 16), g);
        } else {                                // B: 128 rows x 8 chunks
            int cc = c - 2048;
            int row = cc >> 3, ch = cc & 7;
            const unsigned short* g = Wp + (size_t)row * INF + kcol + ch * 8;
            cp_async_16(stage + A_BYTES + SMEM_SWIZZLE_128B(row * 128 + ch * 16), g);
        }
    }
    CP_ASYNC_COMMIT();
}

__global__ void __launch_bounds__(256, 1)
gemm_kernel(const float* __restrict__ bias, float* __restrict__ out) {
    extern __shared__ char smem[];
    const uint32_t sbase = smem_to_u32(smem);
    const int tid  = threadIdx.x;
    const int wid  = tid >> 5;
    const int lane = tid & 31;
    const int wm = wid & 3;       // 4 warps along M
    const int wn = wid >> 2;      // 2 warps along N

    // L2-friendly raster: GROUP=8 m-tiles per n-sweep
    const int grid_n = OUTF / CTA_N;   // 32
    const int GROUP  = 8;
    const int per    = GROUP * grid_n; // 256
    const int g      = blockIdx.x / per;
    const int rem    = blockIdx.x % per;
    const int mtile  = g * GROUP + (rem % GROUP);
    const int ntile  = rem / GROUP;
    const int m0 = mtile * CTA_M;
    const int n0 = ntile * CTA_N;

    const unsigned short* Xp = g_Xh + (size_t)m0 * INF;
    const unsigned short* Wp = reinterpret_cast<const unsigned short*>(g_Wh)
                             + (size_t)n0 * INF;

    // per-lane ldmatrix base offsets (pre-swizzle, within A / B regions)
    const int a_base = (wm * 64 + (lane & 15)) * 128 + ((lane >> 4) << 4);
    const int b_base = (wn * 64 + ((lane >> 4) << 3) + (lane & 7)) * 128
                     + (((lane >> 3) & 1) << 4);

    float acc[4][8][4];
#pragma unroll
    for (int mt = 0; mt < 4; mt++)
#pragma unroll
        for (int nt = 0; nt < 8; nt++)
#pragma unroll
            for (int k = 0; k < 4; k++) acc[mt][nt][k] = 0.f;

    // prologue: fill 3 of 4 stages
    load_stage(sbase, tid, Xp, Wp, 0, 0);
    load_stage(sbase, tid, Xp, Wp, 1, 1);
    load_stage(sbase, tid, Xp, Wp, 2, 2);

    uint32_t a[2][4][4], b[2][4][4];

    for (int it = 0; it < KITERS; it++) {
        CP_ASYNC_WAIT(2);            // stage `it` data resident
        __syncthreads();             // all warps done with stage it-1 too

        // prefetch next K-tile into the free slot
        if (it + 3 < KITERS) {
            load_stage(sbase, tid, Xp, Wp, (it + 3) & 3, it + 3);
        } else {
            CP_ASYNC_COMMIT();       // keep group bookkeeping uniform
        }

        const uint32_t SA = sbase + (it & 3) * STAGE_BYTES;
        const uint32_t SB = SA + A_BYTES;

        // preload ks=0 fragments
#pragma unroll
        for (int mt = 0; mt < 4; mt++)
            ldsm_x4(a[0][mt], SA + SMEM_SWIZZLE_128B(a_base + mt * 2048));
#pragma unroll
        for (int bt = 0; bt < 4; bt++)
            ldsm_x4(b[0][bt], SB + SMEM_SWIZZLE_128B(b_base + bt * 2048));

#pragma unroll
        for (int ks = 0; ks < 4; ks++) {
            const int cur = ks & 1, nxt = cur ^ 1;
            if (ks < 3) {            // prefetch ks+1 fragments behind the mmas
#pragma unroll
                for (int mt = 0; mt < 4; mt++)
                    ldsm_x4(a[nxt][mt],
                            SA + SMEM_SWIZZLE_128B(a_base + mt * 2048 + (ks + 1) * 32));
#pragma unroll
                for (int bt = 0; bt < 4; bt++)
                    ldsm_x4(b[nxt][bt],
                            SB + SMEM_SWIZZLE_128B(b_base + bt * 2048 + (ks + 1) * 32));
            }
#pragma unroll
            for (int mt = 0; mt < 4; mt++)
#pragma unroll
                for (int nt = 0; nt < 8; nt++) {
                    int bt = nt >> 1, pr = nt & 1;
                    mma16816(acc[mt][nt], a[cur][mt],
                             b[cur][bt][pr * 2], b[cur][bt][pr * 2 + 1]);
                }
        }
    }

    // ---------------- epilogue: add bias, store f32 -------------------------
    {
        float2 bv[8];
#pragma unroll
        for (int nt = 0; nt < 8; nt++) {
            int n = n0 + wn * 64 + nt * 8 + (lane & 3) * 2;
            bv[nt].x = __ldg(bias + n);
            bv[nt].y = __ldg(bias + n + 1);
        }
#pragma unroll
        for (int mt = 0; mt < 4; mt++) {
#pragma unroll
            for (int r = 0; r < 2; r++) {
                int row = m0 + wm * 64 + mt * 16 + (lane >> 2) + r * 8;
                float* orow = out + (size_t)row * OUTF + n0 + wn * 64 + (lane & 3) * 2;
#pragma unroll
                for (int nt = 0; nt < 8; nt++) {
                    float2 v;
                    v.x = acc[mt][nt][r * 2 + 0] + bv[nt].x;
                    v.y = acc[mt][nt][r * 2 + 1] + bv[nt].y;
                    *reinterpret_cast<float2*>(orow + nt * 8) = v;
                }
            }
        }
    }
}

// ---------------- launcher --------------------------------------------------
extern "C" void kernel_launch(void* const* d_in, const int* in_sizes, int n_in,
                              void* d_out, int out_size) {
    const float* x    = (const float*)d_in[0];      // [8192, 4096] f32
    const float* w    = (const float*)d_in[1];      // [NNZ] f32
    const float* bias = (const float*)d_in[2];      // [4096] f32
    const void*  idx  = d_in[3];                    // [2, NNZ] int32 OR int64
    float* out = (float*)d_out;                     // [8192, 4096] f32
    const int nnz = in_sizes[1];

    // 1) zero fp16 W (+ reset dtype flag)
    zero_wh_kernel<<<((size_t)OUTF * INF / 8 / 2) / 256, 256>>>();
    // 2) detect int32-vs-int64 indices (64K-entry prefix is conclusive)
    const int ndet = nnz < 65536 ? nnz : 65536;
    detect_idx_kernel<<<(ndet + 255) / 256, 256>>>((const long long*)idx, ndet);
    // 3) scatter-add COO straight into fp16 W (duplicates summed, f16 atomics)
    scatter_kernel<<<(nnz + 255) / 256, 256>>>(idx, w, nnz);
    // 4) convert x to fp16
    convert_x_kernel<<<((size_t)TOKENS * INF / 4 / 4) / 256, 256>>>(x);

    // 5) HMMA GEMM: out = x @ W^T + bias
    cudaFuncSetAttribute(gemm_kernel,
                         cudaFuncAttributeMaxDynamicSharedMemorySize, GEMM_SMEM);
    const int grid = (TOKENS / CTA_M) * (OUTF / CTA_N);  // 32 * 32 = 1024
    gemm_kernel<<<grid, 256, GEMM_SMEM>>>(bias, out);
}

// round 11
// speedup vs baseline: 1.1529x; 1.0109x over previous
#include <cuda_runtime.h>
#include <cuda_fp16.h>
#include <cstdint>

// Problem constants (fixed shapes per reference)
#define TOKENS 8192
#define INF    4096
#define OUTF   4096

// ---------------- device scratch (static globals; no runtime allocation) ----
__device__ __half         g_Wh[(size_t)OUTF * INF];     // 32 MiB fp16 W (scatter target)
__device__ unsigned short g_Xh[(size_t)TOKENS * INF];   // 64 MiB fp16 x
__device__ int            g_idx32_flag;                 // 1 => indices are int32

// ---------------- helpers ---------------------------------------------------
__device__ __forceinline__ uint32_t smem_to_u32(const void* p) {
    uint32_t a;
    asm("{ .reg .u64 t; cvta.to.shared.u64 t, %1; cvt.u32.u64 %0, t; }"
        : "=r"(a) : "l"(p));
    return a;
}

#define SMEM_SWIZZLE_128B(byte_offset) \
    ((byte_offset) ^ (((byte_offset) >> 3) & 0x70))

__device__ __forceinline__ void cp_async_16(uint32_t saddr, const void* gaddr) {
    asm volatile("cp.async.cg.shared.global [%0], [%1], 16;"
                 :: "r"(saddr), "l"(gaddr) : "memory");
}
#define CP_ASYNC_COMMIT() asm volatile("cp.async.commit_group;" ::: "memory")
#define CP_ASYNC_WAIT(N)  asm volatile("cp.async.wait_group %0;" :: "n"(N) : "memory")

__device__ __forceinline__ void ldsm_x4(uint32_t r[4], uint32_t addr) {
    asm volatile("ldmatrix.sync.aligned.m8n8.x4.shared.b16 {%0,%1,%2,%3}, [%4];"
                 : "=r"(r[0]), "=r"(r[1]), "=r"(r[2]), "=r"(r[3]) : "r"(addr));
}

__device__ __forceinline__ void mma16816(float c[4], const uint32_t a[4],
                                         uint32_t b0, uint32_t b1) {
    asm volatile(
        "mma.sync.aligned.m16n8k16.row.col.f32.f16.f16.f32 "
        "{%0,%1,%2,%3}, {%4,%5,%6,%7}, {%8,%9}, {%0,%1,%2,%3};"
        : "+f"(c[0]), "+f"(c[1]), "+f"(c[2]), "+f"(c[3])
        : "r"(a[0]), "r"(a[1]), "r"(a[2]), "r"(a[3]), "r"(b0), "r"(b1));
}

// ---------------- prep kernels ---------------------------------------------
__global__ void flag_reset_kernel() {
    if (threadIdx.x == 0) g_idx32_flag = 0;
}

__device__ __forceinline__ uint2 f4_to_h4(float4 v) {
    __half2 lo = __floats2half2_rn(v.x, v.y);
    __half2 hi = __floats2half2_rn(v.z, v.w);
    uint2 o;
    o.x = *reinterpret_cast<uint32_t*>(&lo);
    o.y = *reinterpret_cast<uint32_t*>(&hi);
    return o;
}

// One block-partitioned kernel running three independent DRAM-bound jobs
// concurrently: convert x -> fp16 (blocks [0,8192)), zero fp16 W (blocks
// [8192,9216)), detect index dtype on a 64K prefix (blocks [9216,9472)).
// Dtype detection: reading the prefix as int64 is in-bounds under both
// interpretations; true-int64 row indices are < OUTF, packed-int32 pairs
// overflow OUTF as soon as the high 32-bit lane is nonzero.
static constexpr int CONV_BLOCKS = 8192;
static constexpr int ZERO_BLOCKS = 1024;
static constexpr int DET_BLOCKS  = 256;

__global__ void fused_prep_kernel(const float* __restrict__ x,
                                  const long long* __restrict__ idx, int ndet) {
    const int b = blockIdx.x;
    if (b < CONV_BLOCKS) {
        // convert: 8.39M float4 -> uint2, ILP x4
        size_t i = (size_t)b * 256 + threadIdx.x;
        const size_t stride = (size_t)CONV_BLOCKS * 256;   // 2.097M
        float4 v0 = reinterpret_cast<const float4*>(x)[i];
        float4 v1 = reinterpret_cast<const float4*>(x)[i + stride];
        float4 v2 = reinterpret_cast<const float4*>(x)[i + 2 * stride];
        float4 v3 = reinterpret_cast<const float4*>(x)[i + 3 * stride];
        reinterpret_cast<uint2*>(g_Xh)[i]              = f4_to_h4(v0);
        reinterpret_cast<uint2*>(g_Xh)[i + stride]     = f4_to_h4(v1);
        reinterpret_cast<uint2*>(g_Xh)[i + 2 * stride] = f4_to_h4(v2);
        reinterpret_cast<uint2*>(g_Xh)[i + 3 * stride] = f4_to_h4(v3);
    } else if (b < CONV_BLOCKS + ZERO_BLOCKS) {
        // zero fp16 W: 2.097M uint4 stores, 8 per thread
        size_t i = (size_t)(b - CONV_BLOCKS) * 256 + threadIdx.x;
        const size_t stride = (size_t)ZERO_BLOCKS * 256;   // 262144
        uint4 z = make_uint4(0u, 0u, 0u, 0u);
#pragma unroll
        for (int j = 0; j < 8; j++)
            reinterpret_cast<uint4*>(g_Wh)[i + j * stride] = z;
    } else {
        int i = (b - CONV_BLOCKS - ZERO_BLOCKS) * 256 + threadIdx.x;
        if (i < ndet) {
            long long v = idx[i];
            if (v < 0 || v >= OUTF) atomicOr(&g_idx32_flag, 1);
        }
    }
}

// Scatter-add COO directly into fp16 W (duplicates summed via f16 atomics).
__global__ void scatter_kernel(const void* __restrict__ idx_raw,
                               const float* __restrict__ w, int nnz) {
    int i = blockIdx.x * blockDim.x + threadIdx.x;
    if (i >= nnz) return;
    long long r, c;
    if (g_idx32_flag) {
        const int* p = (const int*)idx_raw;
        r = p[i];
        c = p[(size_t)nnz + i];
    } else {
        const long long* p = (const long long*)idx_raw;
        r = p[i];
        c = p[(size_t)nnz + i];
    }
    if (r >= 0 && r < OUTF && c >= 0 && c < INF)
        atomicAdd(&g_Wh[(size_t)r * INF + c], __float2half(w[i]));
}

// ---------------- GEMM kernel (mma.sync m16n8k16, Ampere-style) -------------
// CTA tile 256(M) x 128(N) x 64(K); 8 warps as 4(M) x 2(N), warp tile 64x64.
// 4-stage cp.async pipeline; smem rows are 64 halves = 128 B, SW128-swizzled.
// Inner loop register-double-buffers ldmatrix fragments against the HMMAs.

static constexpr int CTA_M  = 256;
static constexpr int CTA_N  = 128;
static constexpr int CTA_K  = 64;
static constexpr int KITERS = INF / CTA_K;   // 64

static constexpr int A_BYTES      = CTA_M * CTA_K * 2;    // 32768
static constexpr int B_BYTES      = CTA_N * CTA_K * 2;    // 16384
static constexpr int STAGE_BYTES  = A_BYTES + B_BYTES;    // 49152
static constexpr int GEMM_SMEM    = 4 * STAGE_BYTES;      // 196608

__device__ __forceinline__ void load_stage(uint32_t sbase, int tid,
                                           const unsigned short* __restrict__ Xp,
                                           const unsigned short* __restrict__ Wp,
                                           int slot, int kb) {
    const uint32_t stage = sbase + slot * STAGE_BYTES;
    const int kcol = kb * CTA_K;
#pragma unroll
    for (int j = 0; j < 12; j++) {              // 3072 16B chunks / 256 threads
        int c = tid + j * 256;
        if (c < 2048) {                         // A: 256 rows x 8 chunks
            int row = c >> 3, ch = c & 7;
            const unsigned short* g = Xp + (size_t)row * INF + kcol + ch * 8;
            cp_async_16(stage + SMEM_SWIZZLE_128B(row * 128 + ch * 16), g);
        } else {                                // B: 128 rows x 8 chunks
            int cc = c - 2048;
            int row = cc >> 3, ch = cc & 7;
            const unsigned short* g = Wp + (size_t)row * INF + kcol + ch * 8;
            cp_async_16(stage + A_BYTES + SMEM_SWIZZLE_128B(row * 128 + ch * 16), g);
        }
    }
    CP_ASYNC_COMMIT();
}

__global__ void __launch_bounds__(256, 1)
gemm_kernel(const float* __restrict__ bias, float* __restrict__ out) {
    extern __shared__ char smem[];
    const uint32_t sbase = smem_to_u32(smem);
    const int tid  = threadIdx.x;
    const int wid  = tid >> 5;
    const int lane = tid & 31;
    const int wm = wid & 3;       // 4 warps along M
    const int wn = wid >> 2;      // 2 warps along N

    // L2-friendly raster: GROUP=16 m-tiles per n-sweep (W DRAM reads halve)
    const int grid_n = OUTF / CTA_N;   // 32
    const int GROUP  = 16;
    const int per    = GROUP * grid_n; // 512
    const int g      = blockIdx.x / per;
    const int rem    = blockIdx.x % per;
    const int mtile  = g * GROUP + (rem % GROUP);
    const int ntile  = rem / GROUP;
    const int m0 = mtile * CTA_M;
    const int n0 = ntile * CTA_N;

    const unsigned short* Xp = g_Xh + (size_t)m0 * INF;
    const unsigned short* Wp = reinterpret_cast<const unsigned short*>(g_Wh)
                             + (size_t)n0 * INF;

    // per-lane ldmatrix base offsets (pre-swizzle, within A / B regions)
    const int a_base = (wm * 64 + (lane & 15)) * 128 + ((lane >> 4) << 4);
    const int b_base = (wn * 64 + ((lane >> 4) << 3) + (lane & 7)) * 128
                     + (((lane >> 3) & 1) << 4);

    float acc[4][8][4];
#pragma unroll
    for (int mt = 0; mt < 4; mt++)
#pragma unroll
        for (int nt = 0; nt < 8; nt++)
#pragma unroll
            for (int k = 0; k < 4; k++) acc[mt][nt][k] = 0.f;

    // prologue: fill 3 of 4 stages
    load_stage(sbase, tid, Xp, Wp, 0, 0);
    load_stage(sbase, tid, Xp, Wp, 1, 1);
    load_stage(sbase, tid, Xp, Wp, 2, 2);

    uint32_t a[2][4][4], b[2][4][4];

    for (int it = 0; it < KITERS; it++) {
        CP_ASYNC_WAIT(2);            // stage `it` data resident
        __syncthreads();             // all warps done with stage it-1 too

        // prefetch next K-tile into the free slot
        if (it + 3 < KITERS) {
            load_stage(sbase, tid, Xp, Wp, (it + 3) & 3, it + 3);
        } else {
            CP_ASYNC_COMMIT();       // keep group bookkeeping uniform
        }

        const uint32_t SA = sbase + (it & 3) * STAGE_BYTES;
        const uint32_t SB = SA + A_BYTES;

        // preload ks=0 fragments
#pragma unroll
        for (int mt = 0; mt < 4; mt++)
            ldsm_x4(a[0][mt], SA + SMEM_SWIZZLE_128B(a_base + mt * 2048));
#pragma unroll
        for (int bt = 0; bt < 4; bt++)
            ldsm_x4(b[0][bt], SB + SMEM_SWIZZLE_128B(b_base + bt * 2048));

#pragma unroll
        for (int ks = 0; ks < 4; ks++) {
            const int cur = ks & 1, nxt = cur ^ 1;
            if (ks < 3) {            // prefetch ks+1 fragments behind the mmas
#pragma unroll
                for (int mt = 0; mt < 4; mt++)
                    ldsm_x4(a[nxt][mt],
                            SA + SMEM_SWIZZLE_128B(a_base + mt * 2048 + (ks + 1) * 32));
#pragma unroll
                for (int bt = 0; bt < 4; bt++)
                    ldsm_x4(b[nxt][bt],
                            SB + SMEM_SWIZZLE_128B(b_base + bt * 2048 + (ks + 1) * 32));
            }
#pragma unroll
            for (int mt = 0; mt < 4; mt++)
#pragma unroll
                for (int nt = 0; nt < 8; nt++) {
                    int bt = nt >> 1, pr = nt & 1;
                    mma16816(acc[mt][nt], a[cur][mt],
                             b[cur][bt][pr * 2], b[cur][bt][pr * 2 + 1]);
                }
        }
    }

    // ---------------- epilogue: add bias, store f32 -------------------------
    {
        float2 bv[8];
#pragma unroll
        for (int nt = 0; nt < 8; nt++) {
            int n = n0 + wn * 64 + nt * 8 + (lane & 3) * 2;
            bv[nt].x = __ldg(bias + n);
            bv[nt].y = __ldg(bias + n + 1);
        }
#pragma unroll
        for (int mt = 0; mt < 4; mt++) {
#pragma unroll
            for (int r = 0; r < 2; r++) {
                int row = m0 + wm * 64 + mt * 16 + (lane >> 2) + r * 8;
                float* orow = out + (size_t)row * OUTF + n0 + wn * 64 + (lane & 3) * 2;
#pragma unroll
                for (int nt = 0; nt < 8; nt++) {
                    float2 v;
                    v.x = acc[mt][nt][r * 2 + 0] + bv[nt].x;
                    v.y = acc[mt][nt][r * 2 + 1] + bv[nt].y;
                    *reinterpret_cast<float2*>(orow + nt * 8) = v;
                }
            }
        }
    }
}

// ---------------- launcher --------------------------------------------------
extern "C" void kernel_launch(void* const* d_in, const int* in_sizes, int n_in,
                              void* d_out, int out_size) {
    const float* x    = (const float*)d_in[0];      // [8192, 4096] f32
    const float* w    = (const float*)d_in[1];      // [NNZ] f32
    const float* bias = (const float*)d_in[2];      // [4096] f32
    const void*  idx  = d_in[3];                    // [2, NNZ] int32 OR int64
    float* out = (float*)d_out;                     // [8192, 4096] f32
    const int nnz = in_sizes[1];

    // 1) reset dtype flag (tiny; also makes GEMM launch #4 for ncu)
    flag_reset_kernel<<<1, 32>>>();
    // 2) fused prep: convert x, zero fp16 W, detect int32-vs-int64 indices
    const int ndet = nnz < 65536 ? nnz : 65536;
    fused_prep_kernel<<<CONV_BLOCKS + ZERO_BLOCKS + DET_BLOCKS, 256>>>(
        x, (const long long*)idx, ndet);
    // 3) scatter-add COO straight into fp16 W (duplicates summed, f16 atomics)
    scatter_kernel<<<(nnz + 255) / 256, 256>>>(idx, w, nnz);

    // 4) HMMA GEMM: out = x @ W^T + bias
    cudaFuncSetAttribute(gemm_kernel,
                         cudaFuncAttributeMaxDynamicSharedMemorySize, GEMM_SMEM);
    const int grid = (TOKENS / CTA_M) * (OUTF / CTA_N);  // 32 * 32 = 1024
    gemm_kernel<<<grid, 256, GEMM_SMEM>>>(bias, out);
}

// round 12
// speedup vs baseline: 1.1691x; 1.0140x over previous
#include <cuda_runtime.h>
#include <cuda_fp16.h>
#include <cstdint>

// Problem constants (fixed shapes per reference)
#define TOKENS 8192
#define INF    4096
#define OUTF   4096

// ---------------- device scratch (static globals; no runtime allocation) ----
__device__ __half         g_Wh[(size_t)OUTF * INF];     // 32 MiB fp16 W (scatter target)
__device__ unsigned short g_Xh[(size_t)TOKENS * INF];   // 64 MiB fp16 x
__device__ int            g_idx32_flag;                 // 1 => indices are int32

// ---------------- helpers ---------------------------------------------------
__device__ __forceinline__ uint32_t smem_to_u32(const void* p) {
    uint32_t a;
    asm("{ .reg .u64 t; cvta.to.shared.u64 t, %1; cvt.u32.u64 %0, t; }"
        : "=r"(a) : "l"(p));
    return a;
}

#define SMEM_SWIZZLE_128B(byte_offset) \
    ((byte_offset) ^ (((byte_offset) >> 3) & 0x70))

__device__ __forceinline__ void cp_async_16(uint32_t saddr, const void* gaddr) {
    asm volatile("cp.async.cg.shared.global [%0], [%1], 16;"
                 :: "r"(saddr), "l"(gaddr) : "memory");
}
#define CP_ASYNC_COMMIT() asm volatile("cp.async.commit_group;" ::: "memory")
#define CP_ASYNC_WAIT(N)  asm volatile("cp.async.wait_group %0;" :: "n"(N) : "memory")

__device__ __forceinline__ void ldsm_x4(uint32_t r[4], uint32_t addr) {
    asm volatile("ldmatrix.sync.aligned.m8n8.x4.shared.b16 {%0,%1,%2,%3}, [%4];"
                 : "=r"(r[0]), "=r"(r[1]), "=r"(r[2]), "=r"(r[3]) : "r"(addr));
}

__device__ __forceinline__ void mma16816(float c[4], const uint32_t a[4],
                                         uint32_t b0, uint32_t b1) {
    asm volatile(
        "mma.sync.aligned.m16n8k16.row.col.f32.f16.f16.f32 "
        "{%0,%1,%2,%3}, {%4,%5,%6,%7}, {%8,%9}, {%0,%1,%2,%3};"
        : "+f"(c[0]), "+f"(c[1]), "+f"(c[2]), "+f"(c[3])
        : "r"(a[0]), "r"(a[1]), "r"(a[2]), "r"(a[3]), "r"(b0), "r"(b1));
}

// ---------------- prep kernels ---------------------------------------------
__global__ void flag_reset_kernel() {
    if (threadIdx.x == 0) g_idx32_flag = 0;
}

__device__ __forceinline__ uint2 f4_to_h4(float4 v) {
    __half2 lo = __floats2half2_rn(v.x, v.y);
    __half2 hi = __floats2half2_rn(v.z, v.w);
    uint2 o;
    o.x = *reinterpret_cast<uint32_t*>(&lo);
    o.y = *reinterpret_cast<uint32_t*>(&hi);
    return o;
}

// One block-partitioned kernel running three independent DRAM-bound jobs
// concurrently: convert x -> fp16, zero fp16 W, detect index dtype on a 64K
// prefix. Dtype detection: reading the prefix as int64 is in-bounds under
// both interpretations; true-int64 row indices are < OUTF, packed-int32
// pairs overflow OUTF as soon as the high 32-bit lane is nonzero.
static constexpr int CONV_BLOCKS = 8192;
static constexpr int ZERO_BLOCKS = 1024;
static constexpr int DET_BLOCKS  = 256;

__global__ void fused_prep_kernel(const float* __restrict__ x,
                                  const long long* __restrict__ idx, int ndet) {
    const int b = blockIdx.x;
    if (b < CONV_BLOCKS) {
        size_t i = (size_t)b * 256 + threadIdx.x;
        const size_t stride = (size_t)CONV_BLOCKS * 256;
        float4 v0 = reinterpret_cast<const float4*>(x)[i];
        float4 v1 = reinterpret_cast<const float4*>(x)[i + stride];
        float4 v2 = reinterpret_cast<const float4*>(x)[i + 2 * stride];
        float4 v3 = reinterpret_cast<const float4*>(x)[i + 3 * stride];
        reinterpret_cast<uint2*>(g_Xh)[i]              = f4_to_h4(v0);
        reinterpret_cast<uint2*>(g_Xh)[i + stride]     = f4_to_h4(v1);
        reinterpret_cast<uint2*>(g_Xh)[i + 2 * stride] = f4_to_h4(v2);
        reinterpret_cast<uint2*>(g_Xh)[i + 3 * stride] = f4_to_h4(v3);
    } else if (b < CONV_BLOCKS + ZERO_BLOCKS) {
        size_t i = (size_t)(b - CONV_BLOCKS) * 256 + threadIdx.x;
        const size_t stride = (size_t)ZERO_BLOCKS * 256;
        uint4 z = make_uint4(0u, 0u, 0u, 0u);
#pragma unroll
        for (int j = 0; j < 8; j++)
            reinterpret_cast<uint4*>(g_Wh)[i + j * stride] = z;
    } else {
        int i = (b - CONV_BLOCKS - ZERO_BLOCKS) * 256 + threadIdx.x;
        if (i < ndet) {
            long long v = idx[i];
            if (v < 0 || v >= OUTF) atomicOr(&g_idx32_flag, 1);
        }
    }
}

// Scatter-add COO directly into fp16 W (duplicates summed via f16 atomics).
__global__ void scatter_kernel(const void* __restrict__ idx_raw,
                               const float* __restrict__ w, int nnz) {
    int i = blockIdx.x * blockDim.x + threadIdx.x;
    if (i >= nnz) return;
    long long r, c;
    if (g_idx32_flag) {
        const int* p = (const int*)idx_raw;
        r = p[i];
        c = p[(size_t)nnz + i];
    } else {
        const long long* p = (const long long*)idx_raw;
        r = p[i];
        c = p[(size_t)nnz + i];
    }
    if (r >= 0 && r < OUTF && c >= 0 && c < INF)
        atomicAdd(&g_Wh[(size_t)r * INF + c], __float2half(w[i]));
}

// ---------------- GEMM kernel (mma.sync m16n8k16, Ampere-style) -------------
// CTA tile 256(M) x 128(N) x 128(K); 8 warps as 4(M) x 2(N), warp tile 64x64.
// 2-stage (96 KB each) cp.async double buffer -> only 32 barrier bubbles.
// Each stage holds two 64-half sub-tiles laid out exactly like the old
// K=64 stages (128B SW128 rows), so descriptors/addressing are unchanged.
// Inner loop register-double-buffers ldmatrix fragments across 8 sub-steps.

static constexpr int CTA_M  = 256;
static constexpr int CTA_N  = 128;
static constexpr int CTA_K  = 128;
static constexpr int KITERS = INF / CTA_K;   // 32

static constexpr int A_SUB_BYTES  = CTA_M * 64 * 2;       // 32768 per kh
static constexpr int B_SUB_BYTES  = CTA_N * 64 * 2;       // 16384 per kh
static constexpr int A_BYTES      = 2 * A_SUB_BYTES;      // 65536
static constexpr int STAGE_BYTES  = 2 * (A_SUB_BYTES + B_SUB_BYTES);  // 98304
static constexpr int GEMM_SMEM    = 2 * STAGE_BYTES;      // 196608

__device__ __forceinline__ void load_stage(uint32_t sbase, int tid,
                                           const unsigned short* __restrict__ Xp,
                                           const unsigned short* __restrict__ Wp,
                                           int slot, int kb) {
    const uint32_t stage = sbase + slot * STAGE_BYTES;
#pragma unroll
    for (int kh = 0; kh < 2; kh++) {
        const uint32_t abase = stage + kh * A_SUB_BYTES;
        const uint32_t bbase = stage + A_BYTES + kh * B_SUB_BYTES;
        const int kc = kb * CTA_K + kh * 64;
#pragma unroll
        for (int j = 0; j < 12; j++) {          // 3072 16B chunks / 256 threads
            int c = tid + j * 256;
            if (c < 2048) {                     // A sub-tile: 256 rows x 8 chunks
                int row = c >> 3, ch = c & 7;
                const unsigned short* g = Xp + (size_t)row * INF + kc + ch * 8;
                cp_async_16(abase + SMEM_SWIZZLE_128B(row * 128 + ch * 16), g);
            } else {                            // B sub-tile: 128 rows x 8 chunks
                int cc = c - 2048;
                int row = cc >> 3, ch = cc & 7;
                const unsigned short* g = Wp + (size_t)row * INF + kc + ch * 8;
                cp_async_16(bbase + SMEM_SWIZZLE_128B(row * 128 + ch * 16), g);
            }
        }
    }
    CP_ASYNC_COMMIT();
}

__global__ void __launch_bounds__(256, 1)
gemm_kernel(const float* __restrict__ bias, float* __restrict__ out) {
    extern __shared__ char smem[];
    const uint32_t sbase = smem_to_u32(smem);
    const int tid  = threadIdx.x;
    const int wid  = tid >> 5;
    const int lane = tid & 31;
    const int wm = wid & 3;       // 4 warps along M
    const int wn = wid >> 2;      // 2 warps along N

    // L2-friendly raster: GROUP=16 m-tiles per n-sweep
    const int grid_n = OUTF / CTA_N;   // 32
    const int GROUP  = 16;
    const int per    = GROUP * grid_n; // 512
    const int g      = blockIdx.x / per;
    const int rem    = blockIdx.x % per;
    const int mtile  = g * GROUP + (rem % GROUP);
    const int ntile  = rem / GROUP;
    const int m0 = mtile * CTA_M;
    const int n0 = ntile * CTA_N;

    const unsigned short* Xp = g_Xh + (size_t)m0 * INF;
    const unsigned short* Wp = reinterpret_cast<const unsigned short*>(g_Wh)
                             + (size_t)n0 * INF;

    // per-lane ldmatrix base offsets (pre-swizzle, within a 64-half sub-tile)
    const int a_base = (wm * 64 + (lane & 15)) * 128 + ((lane >> 4) << 4);
    const int b_base = (wn * 64 + ((lane >> 4) << 3) + (lane & 7)) * 128
                     + (((lane >> 3) & 1) << 4);

    float acc[4][8][4];
#pragma unroll
    for (int mt = 0; mt < 4; mt++)
#pragma unroll
        for (int nt = 0; nt < 8; nt++)
#pragma unroll
            for (int k = 0; k < 4; k++) acc[mt][nt][k] = 0.f;

    // prologue: load first K-tile into slot 0
    load_stage(sbase, tid, Xp, Wp, 0, 0);

    uint32_t a[2][4][4], b[2][4][4];

    for (int it = 0; it < KITERS; it++) {
        CP_ASYNC_WAIT(0);            // tile `it` fully resident
        __syncthreads();             // all warps finished reading the other slot

        const uint32_t S  = sbase + (it & 1) * STAGE_BYTES;
        const uint32_t SBB = S + A_BYTES;

        // preload sub-step 0 fragments FIRST (critical path for the MMAs)
#pragma unroll
        for (int mt = 0; mt < 4; mt++)
            ldsm_x4(a[0][mt], S + SMEM_SWIZZLE_128B(a_base + mt * 2048));
#pragma unroll
        for (int bt = 0; bt < 4; bt++)
            ldsm_x4(b[0][bt], SBB + SMEM_SWIZZLE_128B(b_base + bt * 2048));

        // then kick off the next K-tile load into the other slot
        if (it + 1 < KITERS)
            load_stage(sbase, tid, Xp, Wp, (it + 1) & 1, it + 1);
        else
            CP_ASYNC_COMMIT();       // keep group bookkeeping uniform

        // 8 sub-steps: u = kh*4 + ks over (kh in [0,2), ks in [0,4))
#pragma unroll
        for (int u = 0; u < 8; u++) {
            const int cur = u & 1, nxt = cur ^ 1;
            if (u < 7) {             // prefetch u+1 fragments behind the mmas
                const int kh = (u + 1) >> 2, ks = (u + 1) & 3;
#pragma unroll
                for (int mt = 0; mt < 4; mt++)
                    ldsm_x4(a[nxt][mt], S + kh * A_SUB_BYTES +
                            SMEM_SWIZZLE_128B(a_base + mt * 2048 + ks * 32));
#pragma unroll
                for (int bt = 0; bt < 4; bt++)
                    ldsm_x4(b[nxt][bt], SBB + kh * B_SUB_BYTES +
                            SMEM_SWIZZLE_128B(b_base + bt * 2048 + ks * 32));
            }
#pragma unroll
            for (int mt = 0; mt < 4; mt++)
#pragma unroll
                for (int nt = 0; nt < 8; nt++) {
                    int bt = nt >> 1, pr = nt & 1;
                    mma16816(acc[mt][nt], a[cur][mt],
                             b[cur][bt][pr * 2], b[cur][bt][pr * 2 + 1]);
                }
        }
    }

    // ---------------- epilogue: add bias, store f32 -------------------------
    {
        float2 bv[8];
#pragma unroll
        for (int nt = 0; nt < 8; nt++) {
            int n = n0 + wn * 64 + nt * 8 + (lane & 3) * 2;
            bv[nt].x = __ldg(bias + n);
            bv[nt].y = __ldg(bias + n + 1);
        }
#pragma unroll
        for (int mt = 0; mt < 4; mt++) {
#pragma unroll
            for (int r = 0; r < 2; r++) {
                int row = m0 + wm * 64 + mt * 16 + (lane >> 2) + r * 8;
                float* orow = out + (size_t)row * OUTF + n0 + wn * 64 + (lane & 3) * 2;
#pragma unroll
                for (int nt = 0; nt < 8; nt++) {
                    float2 v;
                    v.x = acc[mt][nt][r * 2 + 0] + bv[nt].x;
                    v.y = acc[mt][nt][r * 2 + 1] + bv[nt].y;
                    *reinterpret_cast<float2*>(orow + nt * 8) = v;
                }
            }
        }
    }
}

// ---------------- launcher --------------------------------------------------
extern "C" void kernel_launch(void* const* d_in, const int* in_sizes, int n_in,
                              void* d_out, int out_size) {
    const float* x    = (const float*)d_in[0];      // [8192, 4096] f32
    const float* w    = (const float*)d_in[1];      // [NNZ] f32
    const float* bias = (const float*)d_in[2];      // [4096] f32
    const void*  idx  = d_in[3];                    // [2, NNZ] int32 OR int64
    float* out = (float*)d_out;                     // [8192, 4096] f32
    const int nnz = in_sizes[1];

    // 1) reset dtype flag
    flag_reset_kernel<<<1, 32>>>();
    // 2) fused prep: convert x, zero fp16 W, detect int32-vs-int64 indices
    const int ndet = nnz < 65536 ? nnz : 65536;
    fused_prep_kernel<<<CONV_BLOCKS + ZERO_BLOCKS + DET_BLOCKS, 256>>>(
        x, (const long long*)idx, ndet);
    // 3) scatter-add COO straight into fp16 W (duplicates summed, f16 atomics)
    scatter_kernel<<<(nnz + 255) / 256, 256>>>(idx, w, nnz);

    // 4) HMMA GEMM: out = x @ W^T + bias
    cudaFuncSetAttribute(gemm_kernel,
                         cudaFuncAttributeMaxDynamicSharedMemorySize, GEMM_SMEM);
    const int grid = (TOKENS / CTA_M) * (OUTF / CTA_N);  // 32 * 32 = 1024
    gemm_kernel<<<grid, 256, GEMM_SMEM>>>(bias, out);
}